// round 3
// baseline (speedup 1.0000x reference)
#include <cuda_runtime.h>

#define BB 4
#define CC 384
#define HH 56
#define WW 56
#define HW (HH*WW)   // 3136
#define KK 5
#define KK2 25
#define SS 7
#define SS2 49
#define D2 192       // C/2
#define SP 52        // s padded to multiple of 4 for float4
#define SPP 53       // smem stride (odd -> conflict-free)

__device__ __align__(16) float g_ctx_p[BB*CC*SS2];
__device__ __align__(16) float g_kf[BB*D2*SS2];
__device__ __align__(16) float g_M[BB*CC*SP];
__device__ __align__(16) float g_dyn[BB*KK2*HW];

// ---------------------------------------------------------------------------
// K1: adaptive avg pool ctx (B,C,56,56) -> ctx_p (B,C,7,7) flattened to 49.
// One block per (b,c) plane; smem per-(row,colbin) partials, then 49 reduces.
// ---------------------------------------------------------------------------
__global__ void pool_kernel(const float* __restrict__ ctx) {
    __shared__ float part[HH][8];
    int t = threadIdx.x;
    int bc = blockIdx.x;
    float* pf = &part[0][0];
    for (int i = t; i < HH*8; i += blockDim.x) pf[i] = 0.f;
    __syncthreads();
    const float* p = ctx + (size_t)bc * HW;
    for (int i = t; i < HW; i += blockDim.x) {
        int h = i / WW, w = i - h*WW;
        atomicAdd(&part[h][w >> 3], p[i]);
    }
    __syncthreads();
    if (t < SS2) {
        int s1 = t / SS, s2 = t - s1*SS;
        float s = 0.f;
        #pragma unroll
        for (int i = 0; i < 8; i++) s += part[s1*8 + i][s2];
        g_ctx_p[(size_t)bc * SS2 + t] = s * (1.f/64.f);
    }
}

// ---------------------------------------------------------------------------
// K2: kf[b,d,s] = sum_c Wk[d,c] * ctx_p[b,c,s]    (tiny GEMM, 29 MF)
// ---------------------------------------------------------------------------
__global__ void kf_kernel(const float* __restrict__ Wk) {
    int id = blockIdx.x * blockDim.x + threadIdx.x;
    if (id >= BB*D2*SS2) return;
    int s = id % SS2;
    int d = (id / SS2) % D2;
    int b = id / (SS2*D2);
    const float* wk = Wk + (size_t)d * CC;
    const float* cp = g_ctx_p + (size_t)b * CC * SS2 + s;
    float acc = 0.f;
    #pragma unroll 8
    for (int c = 0; c < CC; c++) acc += wk[c] * cp[(size_t)c * SS2];
    g_kf[id] = acc;
}

// ---------------------------------------------------------------------------
// K3: M[b,c,s] = sum_d Wq[d,c] * kf[b,d,s], padded to SP=52 (pad cols = 0)
// ---------------------------------------------------------------------------
__global__ void m_kernel(const float* __restrict__ Wq) {
    int id = blockIdx.x * blockDim.x + threadIdx.x;
    if (id >= BB*CC*SP) return;
    int s = id % SP;
    int c = (id / SP) % CC;
    int b = id / (SP*CC);
    float acc = 0.f;
    if (s < SS2) {
        const float* kf = g_kf + (size_t)b * D2 * SS2 + s;
        #pragma unroll 8
        for (int d = 0; d < D2; d++) acc += Wq[(size_t)d * CC + c] * kf[(size_t)d * SS2];
    }
    g_M[id] = acc;
}

// ---------------------------------------------------------------------------
// K4: per pixel n: logits[s] = sum_c x[b,c,n]*M[b,c,s]; softmax over 49;
//     dyn[j] = sum_s Wwd[j,s]*A[s].  Block = 64 pixels x 2 channel-groups.
// ---------------------------------------------------------------------------
__global__ void __launch_bounds__(128) attn_kernel(const float* __restrict__ x,
                                                   const float* __restrict__ Wwd) {
    __shared__ float part[2][64][SPP];
    __shared__ float wwd_s[KK2*SS2];
    int t = threadIdx.x;
    int p = t & 63;
    int g = t >> 6;
    int b = blockIdx.y;
    int n0 = blockIdx.x * 64;

    for (int i = t; i < KK2*SS2; i += 128) wwd_s[i] = Wwd[i];

    float acc[SP];
    #pragma unroll
    for (int s = 0; s < SP; s++) acc[s] = 0.f;

    const float* xb = x + (size_t)b * CC * HW + n0 + p;
    const float4* Mb = (const float4*)(g_M + (size_t)b * CC * SP);
    int c0 = g * (CC/2);
    #pragma unroll 2
    for (int c = c0; c < c0 + CC/2; c++) {
        float xv = __ldg(xb + (size_t)c * HW);
        const float4* mrow = Mb + c * (SP/4);
        #pragma unroll
        for (int v = 0; v < SP/4; v++) {
            float4 m = __ldg(mrow + v);
            acc[4*v+0] += xv * m.x;
            acc[4*v+1] += xv * m.y;
            acc[4*v+2] += xv * m.z;
            acc[4*v+3] += xv * m.w;
        }
    }
    #pragma unroll
    for (int s = 0; s < SP; s++) part[g][p][s] = acc[s];
    __syncthreads();

    // combine the two channel-group partials (disjoint s-ranges per g)
    {
        int sbeg = g * 26;
        for (int s = sbeg; s < sbeg + 26; s++)
            part[0][p][s] = part[0][p][s] + part[1][p][s];
    }
    __syncthreads();

    // softmax per pixel (thread p of group 0, serial over 49)
    if (g == 0) {
        float m = -1e30f;
        for (int s = 0; s < SS2; s++) m = fmaxf(m, part[0][p][s]);
        float sum = 0.f;
        for (int s = 0; s < SS2; s++) {
            float e = __expf(part[0][p][s] - m);
            part[0][p][s] = e;
            sum += e;
        }
        float inv = 1.f / sum;
        for (int s = 0; s < SS2; s++) part[0][p][s] *= inv;
    }
    __syncthreads();

    // dyn projection: j-ranges split across the two groups
    int jbeg = g ? 13 : 0;
    int jend = g ? 25 : 13;
    for (int j = jbeg; j < jend; j++) {
        float dsum = 0.f;
        #pragma unroll 7
        for (int s = 0; s < SS2; s++) dsum += wwd_s[j*SS2 + s] * part[0][p][s];
        g_dyn[((size_t)b*KK2 + j)*HW + n0 + p] = dsum;
    }
}

// ---------------------------------------------------------------------------
// K5: out[b,c,h,w] = sum_{i,j} dyn[b,i*5+j,h,w] * x[b,c,h+i-2,w+j-2] (0-pad)
// Block = (c-group of 96) x (4-row band) x batch. dyn in regs (reused over c),
// one channel's padded rows staged in smem per iteration.
// ---------------------------------------------------------------------------
__global__ void __launch_bounds__(224) taps_kernel(const float* __restrict__ x,
                                                   float* __restrict__ out) {
    __shared__ float xs[8][64];
    int t = threadIdx.x;
    int r = t / WW;            // 0..3
    int w = t - r*WW;          // 0..55
    int b = blockIdx.z;
    int h0 = blockIdx.y * 4;
    int c0 = blockIdx.x * 96;
    int h = h0 + r;
    int n = h*WW + w;

    float dd[KK2];
    #pragma unroll
    for (int j = 0; j < KK2; j++)
        dd[j] = g_dyn[((size_t)b*KK2 + j)*HW + n];

    const float* xb = x + (size_t)b * CC * HW;
    float* ob = out + (size_t)b * CC * HW;

    for (int c = c0; c < c0 + 96; c++) {
        const float* xc = xb + (size_t)c * HW;
        __syncthreads();
        for (int i = t; i < 8*60; i += 224) {
            int rr = i / 60, cc = i - rr*60;
            int gr = h0 + rr - 2, gc = cc - 2;
            float v = 0.f;
            if (gr >= 0 && gr < HH && gc >= 0 && gc < WW) v = xc[gr*WW + gc];
            xs[rr][cc] = v;
        }
        __syncthreads();
        float acc = 0.f;
        #pragma unroll
        for (int i = 0; i < KK; i++) {
            #pragma unroll
            for (int j = 0; j < KK; j++)
                acc += dd[i*KK + j] * xs[r + i][w + j];
        }
        ob[(size_t)c*HW + n] = acc;
    }
}

// ---------------------------------------------------------------------------
extern "C" void kernel_launch(void* const* d_in, const int* in_sizes, int n_in,
                              void* d_out, int out_size) {
    const float* x   = (const float*)d_in[0];
    const float* ctx = (const float*)d_in[1];
    const float* Wq  = (const float*)d_in[2];
    const float* Wk  = (const float*)d_in[3];
    const float* Wwd = (const float*)d_in[4];
    float* out = (float*)d_out;

    pool_kernel<<<BB*CC, 256>>>(ctx);
    kf_kernel<<<(BB*D2*SS2 + 255)/256, 256>>>(Wk);
    m_kernel<<<(BB*CC*SP + 255)/256, 256>>>(Wq);
    attn_kernel<<<dim3(HW/64, BB), 128>>>(x, Wwd);
    taps_kernel<<<dim3(CC/96, HH/4, BB), 224>>>(x, out);
}

// round 4
// speedup vs baseline: 1.8214x; 1.8214x over previous
#include <cuda_runtime.h>

#define BB 4
#define CC 384
#define HH 56
#define WW 56
#define HW (HH*WW)   // 3136
#define KK 5
#define KK2 25
#define SS 7
#define SS2 49
#define D2 192       // C/2
#define SP 52        // s padded to multiple of 4 for float4
#define SPP 53       // part stride (odd -> conflict-free)

__device__ __align__(16) float g_ctx_p[BB*CC*SS2];
__device__ __align__(16) float g_kf[BB*D2*SS2];
__device__ __align__(16) float g_M[BB*CC*SP];
__device__ __align__(16) float g_dyn[BB*KK2*HW];

// ---------------------------------------------------------------------------
// K1: adaptive avg pool ctx (B,C,56,56) -> ctx_p (B,C,7,7)
// ---------------------------------------------------------------------------
__global__ void pool_kernel(const float* __restrict__ ctx) {
    __shared__ float part[HH][8];
    int t = threadIdx.x;
    int bc = blockIdx.x;
    float* pf = &part[0][0];
    for (int i = t; i < HH*8; i += blockDim.x) pf[i] = 0.f;
    __syncthreads();
    const float* p = ctx + (size_t)bc * HW;
    for (int i = t; i < HW; i += blockDim.x) {
        int h = i / WW, w = i - h*WW;
        atomicAdd(&part[h][w >> 3], p[i]);
    }
    __syncthreads();
    if (t < SS2) {
        int s1 = t / SS, s2 = t - s1*SS;
        float s = 0.f;
        #pragma unroll
        for (int i = 0; i < 8; i++) s += part[s1*8 + i][s2];
        g_ctx_p[(size_t)bc * SS2 + t] = s * (1.f/64.f);
    }
}

// ---------------------------------------------------------------------------
// K2: kf[b,d,s] = sum_c Wk[d,c] * ctx_p[b,c,s]
// ---------------------------------------------------------------------------
__global__ void kf_kernel(const float* __restrict__ Wk) {
    int id = blockIdx.x * blockDim.x + threadIdx.x;
    if (id >= BB*D2*SS2) return;
    int s = id % SS2;
    int d = (id / SS2) % D2;
    int b = id / (SS2*D2);
    const float* wk = Wk + (size_t)d * CC;
    const float* cp = g_ctx_p + (size_t)b * CC * SS2 + s;
    float acc = 0.f;
    #pragma unroll 8
    for (int c = 0; c < CC; c++) acc += wk[c] * cp[(size_t)c * SS2];
    g_kf[id] = acc;
}

// ---------------------------------------------------------------------------
// K3: M[b,c,s] = sum_d Wq[d,c] * kf[b,d,s], padded to SP=52 (pad cols = 0)
// ---------------------------------------------------------------------------
__global__ void m_kernel(const float* __restrict__ Wq) {
    int id = blockIdx.x * blockDim.x + threadIdx.x;
    if (id >= BB*CC*SP) return;
    int s = id % SP;
    int c = (id / SP) % CC;
    int b = id / (SP*CC);
    float acc = 0.f;
    if (s < SS2) {
        const float* kf = g_kf + (size_t)b * D2 * SS2 + s;
        #pragma unroll 8
        for (int d = 0; d < D2; d++) acc += Wq[(size_t)d * CC + c] * kf[(size_t)d * SS2];
    }
    g_M[id] = acc;
}

// ---------------------------------------------------------------------------
// K4 v2: 32 pixels x 4 channel-groups per block (128 threads).
// M staged in smem (broadcast LDS, off the LSU). x via LDG, unrolled.
// Dynamic smem layout: Ms[CC*SP] | part[4*32*SPP] | wwd[KK2*SS2]
// ---------------------------------------------------------------------------
__global__ void __launch_bounds__(128) attn_kernel(const float* __restrict__ x,
                                                   const float* __restrict__ Wwd) {
    extern __shared__ float sh[];
    float* Ms    = sh;                       // CC*SP = 19968 floats
    float* part  = Ms + CC*SP;               // 4*32*SPP = 6784 floats
    float* wwd_s = part + 4*32*SPP;          // 1225 floats

    int t = threadIdx.x;
    int p = t & 31;
    int g = t >> 5;
    int b = blockIdx.y;
    int n0 = blockIdx.x * 32;

    // stage M for this batch (float4), and Wwd
    {
        const float4* Mg = (const float4*)(g_M + (size_t)b * CC * SP);
        float4* Ms4 = (float4*)Ms;
        #pragma unroll 4
        for (int i = t; i < CC*(SP/4); i += 128) Ms4[i] = Mg[i];
        for (int i = t; i < KK2*SS2; i += 128) wwd_s[i] = Wwd[i];
    }
    __syncthreads();

    float acc[SP];
    #pragma unroll
    for (int s = 0; s < SP; s++) acc[s] = 0.f;

    const float* xb = x + (size_t)b * CC * HW + n0 + p;
    int c0 = g * 96;
    #pragma unroll 4
    for (int cc = 0; cc < 96; cc++) {
        int c = c0 + cc;
        float xv = __ldg(xb + (size_t)c * HW);
        const float4* mrow = (const float4*)(Ms + c * SP);
        #pragma unroll
        for (int v = 0; v < SP/4; v++) {
            float4 m = mrow[v];
            acc[4*v+0] += xv * m.x;
            acc[4*v+1] += xv * m.y;
            acc[4*v+2] += xv * m.z;
            acc[4*v+3] += xv * m.w;
        }
    }
    // write partials
    {
        float* pr = part + (g*32 + p) * SPP;
        #pragma unroll
        for (int s = 0; s < SP; s++) pr[s] = acc[s];
    }
    __syncthreads();

    // combine 4 groups into group-0 rows (only s < 49 needed)
    for (int i = t; i < 32*SS2; i += 128) {
        int pp = i & 31;
        int s  = i >> 5;        // 0..48
        part[pp*SPP + s] = part[pp*SPP + s] + part[(32+pp)*SPP + s]
                         + part[(64+pp)*SPP + s] + part[(96+pp)*SPP + s];
    }
    __syncthreads();

    // softmax (warp 0, lane p = pixel). exp stored to smem, 1/sum in pad slot.
    if (g == 0) {
        float* row = part + p*SPP;
        float v[SS2];
        #pragma unroll
        for (int s = 0; s < SS2; s++) v[s] = row[s];
        float mx = v[0];
        #pragma unroll
        for (int s = 1; s < SS2; s++) mx = fmaxf(mx, v[s]);
        float sum = 0.f;
        #pragma unroll
        for (int s = 0; s < SS2; s++) { v[s] = __expf(v[s] - mx); sum += v[s]; }
        #pragma unroll
        for (int s = 0; s < SS2; s++) row[s] = v[s];
        row[52] = 1.f / sum;
    }
    __syncthreads();

    // dyn projection: dyn[j] = (sum_s wwd[j,s]*e[s]) * inv
    {
        const float* row = part + p*SPP;
        float inv = row[52];
        for (int j = g; j < KK2; j += 4) {
            const float* ww = wwd_s + j*SS2;
            float d = 0.f;
            #pragma unroll
            for (int s = 0; s < SS2; s++) d += ww[s] * row[s];
            g_dyn[((size_t)b*KK2 + j)*HW + n0 + p] = d * inv;
        }
    }
}

#define ATTN_SMEM ((CC*SP + 4*32*SPP + KK2*SS2) * 4)

// ---------------------------------------------------------------------------
// K5 v2: 2 outputs/thread (dyn in 50 regs reused over 48 channels),
// float2 window loads, 4 channels per barrier pair.
// Block: 224 thr = 8 rows x 28 w-pairs. Grid (8 c-groups, 7 h-bands, B).
// ---------------------------------------------------------------------------
__global__ void __launch_bounds__(224) taps_kernel(const float* __restrict__ x,
                                                   float* __restrict__ out) {
    __shared__ float xs[4][12][66];
    int t = threadIdx.x;
    int r  = t / 28;          // 0..7
    int wp = t - r*28;        // 0..27
    int w0 = wp * 2;
    int b  = blockIdx.z;
    int h0 = blockIdx.y * 8;
    int c0 = blockIdx.x * 48;
    int h = h0 + r;
    int n = h*WW + w0;

    float dd0[KK2], dd1[KK2];
    #pragma unroll
    for (int j = 0; j < KK2; j++) {
        float2 d2 = *(const float2*)(g_dyn + ((size_t)b*KK2 + j)*HW + n);
        dd0[j] = d2.x; dd1[j] = d2.y;
    }

    const float* xb = x + (size_t)b * CC * HW;
    float* ob = out + (size_t)b * CC * HW;

    for (int cq = 0; cq < 48; cq += 4) {
        __syncthreads();
        // stage 4 channels, rows h0-2..h0+9, cols -2..57
        for (int i = t; i < 4*12*60; i += 224) {
            int ci  = i / 720;
            int rem = i - ci*720;
            int rr  = rem / 60;
            int ccol = rem - rr*60;
            int gr = h0 + rr - 2, gc = ccol - 2;
            float v = 0.f;
            if (gr >= 0 && gr < HH && gc >= 0 && gc < WW)
                v = xb[(size_t)(c0+cq+ci)*HW + gr*WW + gc];
            xs[ci][rr][ccol] = v;
        }
        __syncthreads();
        #pragma unroll
        for (int ci = 0; ci < 4; ci++) {
            float a0 = 0.f, a1 = 0.f;
            #pragma unroll
            for (int i = 0; i < KK; i++) {
                const float2* row2 = (const float2*)&xs[ci][r+i][w0];
                float2 v0 = row2[0], v1 = row2[1], v2 = row2[2];
                a0 += dd0[i*5+0]*v0.x + dd0[i*5+1]*v0.y + dd0[i*5+2]*v1.x
                    + dd0[i*5+3]*v1.y + dd0[i*5+4]*v2.x;
                a1 += dd1[i*5+0]*v0.y + dd1[i*5+1]*v1.x + dd1[i*5+2]*v1.y
                    + dd1[i*5+3]*v2.x + dd1[i*5+4]*v2.y;
            }
            float2 o2; o2.x = a0; o2.y = a1;
            *(float2*)(ob + (size_t)(c0+cq+ci)*HW + n) = o2;
        }
    }
}

// ---------------------------------------------------------------------------
extern "C" void kernel_launch(void* const* d_in, const int* in_sizes, int n_in,
                              void* d_out, int out_size) {
    const float* x   = (const float*)d_in[0];
    const float* ctx = (const float*)d_in[1];
    const float* Wq  = (const float*)d_in[2];
    const float* Wk  = (const float*)d_in[3];
    const float* Wwd = (const float*)d_in[4];
    float* out = (float*)d_out;

    static bool attr_set = false;
    if (!attr_set) {
        cudaFuncSetAttribute(attn_kernel,
                             cudaFuncAttributeMaxDynamicSharedMemorySize,
                             ATTN_SMEM);
        attr_set = true;
    }

    pool_kernel<<<BB*CC, 256>>>(ctx);
    kf_kernel<<<(BB*D2*SS2 + 255)/256, 256>>>(Wk);
    m_kernel<<<(BB*CC*SP + 255)/256, 256>>>(Wq);
    attn_kernel<<<dim3(HW/32, BB), 128, ATTN_SMEM>>>(x, Wwd);
    taps_kernel<<<dim3(CC/48, HH/8, BB), 224>>>(x, out);
}

// round 6
// speedup vs baseline: 2.4907x; 1.3675x over previous
#include <cuda_runtime.h>
#include <cstdint>

typedef unsigned long long ull;

#define BB 4
#define CC 384
#define HH 56
#define WW 56
#define HW (HH*WW)   // 3136
#define KK 5
#define KK2 25
#define SS 7
#define SS2 49
#define D2 192
#define SPM 64       // padded M row: 4 segments x 16 slots (14 real + 2 pad)
#define SEG 14

__device__ __align__(16) float g_ctx_p[BB*CC*SS2];
__device__ __align__(16) float g_kf[BB*D2*SS2];
__device__ __align__(16) float g_M[BB*CC*SPM];
__device__ __align__(16) float g_dyn[BB*KK2*HW];

#define FMA2(acc, a, b) asm("fma.rn.f32x2 %0, %1, %2, %0;" : "+l"(acc) : "l"(a), "l"(b))

__device__ __forceinline__ ull packf2(float lo, float hi) {
    ull r;
    asm("mov.b64 %0, {%1, %2};" : "=l"(r) : "r"(__float_as_uint(lo)), "r"(__float_as_uint(hi)));
    return r;
}
__device__ __forceinline__ float2 unpackf2(ull v) {
    uint32_t l, h;
    asm("mov.b64 {%0, %1}, %2;" : "=r"(l), "=r"(h) : "l"(v));
    float2 r; r.x = __uint_as_float(l); r.y = __uint_as_float(h);
    return r;
}

// ---------------------------------------------------------------------------
// K1: adaptive avg pool ctx (B,C,56,56) -> ctx_p (B,C,7,7)
// ---------------------------------------------------------------------------
__global__ void pool_kernel(const float* __restrict__ ctx) {
    __shared__ float part[HH][8];
    int t = threadIdx.x;
    int bc = blockIdx.x;
    float* pf = &part[0][0];
    for (int i = t; i < HH*8; i += blockDim.x) pf[i] = 0.f;
    __syncthreads();
    const float* p = ctx + (size_t)bc * HW;
    for (int i = t; i < HW; i += blockDim.x) {
        int h = i / WW, w = i - h*WW;
        atomicAdd(&part[h][w >> 3], p[i]);
    }
    __syncthreads();
    if (t < SS2) {
        int s1 = t / SS, s2 = t - s1*SS;
        float s = 0.f;
        #pragma unroll
        for (int i = 0; i < 8; i++) s += part[s1*8 + i][s2];
        g_ctx_p[(size_t)bc * SS2 + t] = s * (1.f/64.f);
    }
}

// ---------------------------------------------------------------------------
// K2: kf[b,d,s] = sum_c Wk[d,c] * ctx_p[b,c,s]
// ---------------------------------------------------------------------------
__global__ void kf_kernel(const float* __restrict__ Wk) {
    int id = blockIdx.x * blockDim.x + threadIdx.x;
    if (id >= BB*D2*SS2) return;
    int s = id % SS2;
    int d = (id / SS2) % D2;
    int b = id / (SS2*D2);
    const float* wk = Wk + (size_t)d * CC;
    const float* cp = g_ctx_p + (size_t)b * CC * SS2 + s;
    float acc = 0.f;
    #pragma unroll 8
    for (int c = 0; c < CC; c++) acc += wk[c] * cp[(size_t)c * SS2];
    g_kf[id] = acc;
}

// ---------------------------------------------------------------------------
// K3: M[b,c,slot] with slot = sg*16+k -> s = sg*14+k (k<14, s<49), pads 0
// ---------------------------------------------------------------------------
__global__ void m_kernel(const float* __restrict__ Wq) {
    int id = blockIdx.x * blockDim.x + threadIdx.x;
    if (id >= BB*CC*SPM) return;
    int slot = id % SPM;
    int c = (id / SPM) % CC;
    int b = id / (SPM*CC);
    int sg = slot >> 4, k = slot & 15;
    int s = sg*SEG + k;
    float acc = 0.f;
    if (k < SEG && s < SS2) {
        const float* kf = g_kf + (size_t)b * D2 * SS2 + s;
        #pragma unroll 8
        for (int d = 0; d < D2; d++) acc += Wq[(size_t)d * CC + c] * kf[(size_t)d * SS2];
    }
    g_M[id] = acc;
}

// ---------------------------------------------------------------------------
// K4 v3: register-tiled GEMM logits + fused softmax + dyn projection.
// Block: 112 pixels x 56 s (padded), 224 threads, thread = 2 px x 14 s (f32x2).
// Double-buffered smem chunks (16 c) with register prefetch.
// ---------------------------------------------------------------------------
#define PX 112
#define AT 224
#define KCH 16
#define NCH (CC/KCH)          // 24
#define XS_F (KCH*PX)         // 1792 floats per buffer
#define MS_F (KCH*SPM)        // 1024 floats per buffer
#define PSTR 57
#define ATTN_SMEM ((2*XS_F + 2*MS_F + PX*PSTR + KK2*SS2) * 4)

__global__ void __launch_bounds__(AT) attn_kernel(const float* __restrict__ x,
                                                  const float* __restrict__ Wwd) {
    extern __shared__ float sh[];
    float* xs   = sh;                      // 2*XS_F
    float* ms   = sh + 2*XS_F;             // 2*MS_F
    float* part = ms + 2*MS_F;             // PX*57
    float* wwd  = part + PX*PSTR;          // 1225

    int t = threadIdx.x;
    int sg  = t / 56;       // 0..3
    int pxg = t % 56;       // 0..55
    int b = blockIdx.y;
    int n0 = blockIdx.x * PX;

    for (int i = t; i < KK2*SS2; i += AT) wwd[i] = Wwd[i];

    const float* xb = x + (size_t)b*CC*HW + n0;
    const float4* mb4 = (const float4*)(g_M + (size_t)b*CC*SPM);

    // prefetch slot mapping (constant per thread)
    int xc0 = t / 28, xp0 = t % 28;              // xs slot 0: i = t       (<448)
    int xc1 = (t+224) / 28, xp1 = (t+224) % 28;  // xs slot 1: i = t+224
    // ms slots: j = t (<224) and j = t+224 (<256 -> t<32)

    float4 pf0, pf1, pf2, pf3;
    pf3 = make_float4(0.f,0.f,0.f,0.f);
    // load + store chunk 0 into buffer 0
    pf0 = *(const float4*)(xb + (size_t)xc0*HW + xp0*4);
    pf1 = *(const float4*)(xb + (size_t)xc1*HW + xp1*4);
    pf2 = mb4[t];
    if (t < 32) pf3 = mb4[224 + t];
    {
        float4* xs4 = (float4*)xs;
        float4* ms4 = (float4*)ms;
        xs4[t] = pf0; xs4[t+224] = pf1;
        ms4[t] = pf2;
        if (t < 32) ms4[224 + t] = pf3;
    }

    ull acc0[7], acc1[7];
    #pragma unroll
    for (int j = 0; j < 7; j++) { acc0[j] = 0ULL; acc1[j] = 0ULL; }

    uint32_t xs_sa = (uint32_t)__cvta_generic_to_shared(xs) + (2*pxg)*4;
    uint32_t ms_sa = (uint32_t)__cvta_generic_to_shared(ms) + (sg*16)*4;

    int p = 0;
    for (int ch = 0; ch < NCH; ch++) {
        __syncthreads();
        if (ch + 1 < NCH) {
            const float* xcb = xb + (size_t)(ch+1)*KCH*HW;
            const float4* mcb = mb4 + (ch+1)*(MS_F/4);
            pf0 = *(const float4*)(xcb + (size_t)xc0*HW + xp0*4);
            pf1 = *(const float4*)(xcb + (size_t)xc1*HW + xp1*4);
            pf2 = mcb[t];
            if (t < 32) pf3 = mcb[224 + t];
        }
        uint32_t xsa = xs_sa + p*(XS_F*4);
        uint32_t msa = ms_sa + p*(MS_F*4);
        #pragma unroll
        for (int c = 0; c < KCH; c++) {
            float xv0, xv1;
            asm("ld.shared.v2.f32 {%0, %1}, [%2];"
                : "=f"(xv0), "=f"(xv1) : "r"(xsa + c*(PX*4)));
            ull ax0 = packf2(xv0, xv0);
            ull ax1 = packf2(xv1, xv1);
            ull m0,m1,m2,m3,m4,m5,m6;
            uint32_t ma = msa + c*(SPM*4);
            asm("ld.shared.v2.u64 {%0, %1}, [%2];" : "=l"(m0), "=l"(m1) : "r"(ma));
            asm("ld.shared.v2.u64 {%0, %1}, [%2];" : "=l"(m2), "=l"(m3) : "r"(ma+16));
            asm("ld.shared.v2.u64 {%0, %1}, [%2];" : "=l"(m4), "=l"(m5) : "r"(ma+32));
            asm("ld.shared.u64 %0, [%1];"          : "=l"(m6)           : "r"(ma+48));
            FMA2(acc0[0], ax0, m0);  FMA2(acc1[0], ax1, m0);
            FMA2(acc0[1], ax0, m1);  FMA2(acc1[1], ax1, m1);
            FMA2(acc0[2], ax0, m2);  FMA2(acc1[2], ax1, m2);
            FMA2(acc0[3], ax0, m3);  FMA2(acc1[3], ax1, m3);
            FMA2(acc0[4], ax0, m4);  FMA2(acc1[4], ax1, m4);
            FMA2(acc0[5], ax0, m5);  FMA2(acc1[5], ax1, m5);
            FMA2(acc0[6], ax0, m6);  FMA2(acc1[6], ax1, m6);
        }
        if (ch + 1 < NCH) {
            float4* xs4 = (float4*)(xs + (1-p)*XS_F);
            float4* ms4 = (float4*)(ms + (1-p)*MS_F);
            xs4[t] = pf0; xs4[t+224] = pf1;
            ms4[t] = pf2;
            if (t < 32) ms4[224 + t] = pf3;
        }
        p ^= 1;
    }

    // scatter logits to part
    {
        float* pr0 = part + (2*pxg)*PSTR + sg*SEG;
        float* pr1 = pr0 + PSTR;
        #pragma unroll
        for (int j = 0; j < 7; j++) {
            float2 v0 = unpackf2(acc0[j]);
            float2 v1 = unpackf2(acc1[j]);
            pr0[2*j] = v0.x; pr0[2*j+1] = v0.y;
            pr1[2*j] = v1.x; pr1[2*j+1] = v1.y;
        }
    }
    __syncthreads();

    // softmax per pixel
    if (t < PX) {
        float* row = part + t*PSTR;
        float v[SS2];
        #pragma unroll
        for (int s = 0; s < SS2; s++) v[s] = row[s];
        float mx = v[0];
        #pragma unroll
        for (int s = 1; s < SS2; s++) mx = fmaxf(mx, v[s]);
        float sum = 0.f;
        #pragma unroll
        for (int s = 0; s < SS2; s++) { v[s] = __expf(v[s] - mx); sum += v[s]; }
        #pragma unroll
        for (int s = 0; s < SS2; s++) row[s] = v[s];
        row[56] = 1.f / sum;
    }
    __syncthreads();

    // dyn projection
    for (int idx = t; idx < KK2*PX; idx += AT) {
        int px = idx % PX;
        int j  = idx / PX;
        const float* ww  = wwd + j*SS2;
        const float* row = part + px*PSTR;
        float d = 0.f;
        #pragma unroll
        for (int s = 0; s < SS2; s++) d += ww[s] * row[s];
        g_dyn[((size_t)b*KK2 + j)*HW + n0 + px] = d * row[56];
    }
}

// ---------------------------------------------------------------------------
// K5 v3: f32x2 taps. Thread = 2 outputs (cols w0,w0+1) of row h, 24 channels.
// dyn pairs in 25 ull regs (reused across channels). Double-buffered staging.
// Block: 196 thr = 7 rows x 28 col-pairs. Grid (16 c-grp, 8 bands, B).
// ---------------------------------------------------------------------------
#define TT 196
#define TCG 24          // channels per block
#define TST 6           // stages of 4 channels
#define STG_F2 1320     // float2 per stage buffer: 4*11*30

__global__ void __launch_bounds__(TT, 3) taps_kernel(const float* __restrict__ x,
                                                     float* __restrict__ out) {
    __shared__ float2 xs2[2*STG_F2];
    int t = threadIdx.x;
    int rp = t / 28;           // 0..6
    int wp = t % 28;
    int w0 = wp*2;
    int b  = blockIdx.z;
    int h0 = blockIdx.y * 7;
    int c0 = blockIdx.x * TCG;
    int h  = h0 + rp;

    // dyn coefficient pairs for this thread's 2 pixels
    ull dd[KK2];
    #pragma unroll
    for (int j = 0; j < KK2; j++)
        dd[j] = *(const ull*)(g_dyn + ((size_t)b*KK2 + j)*HW + h*WW + w0);

    // staging slot mapping: idx = t + 196k, k=0..6; layout [ci][rr][q] (float2)
    int sidx[7]; int goff[7]; bool gval[7];
    #pragma unroll
    for (int k = 0; k < 7; k++) {
        int idx = t + TT*k;
        sidx[k] = idx;
        int ci  = idx / 330;
        int rem = idx - ci*330;
        int rr  = rem / 30;
        int q   = rem - rr*30;
        int gr  = h0 + rr - 2;
        int gc  = 2*q - 2;
        gval[k] = (idx < STG_F2) && (gr >= 0) && (gr < HH) && (q >= 1) && (q <= 28);
        goff[k] = ci*HW + gr*WW + gc;
    }

    const float* xb0 = x + (size_t)b*CC*HW + (size_t)c0*HW;
    float* ob = out + (size_t)b*CC*HW;

    float2 pre[7];
    // prefetch + store stage 0
    #pragma unroll
    for (int k = 0; k < 7; k++)
        pre[k] = gval[k] ? *(const float2*)(xb0 + goff[k]) : make_float2(0.f, 0.f);
    #pragma unroll
    for (int k = 0; k < 7; k++)
        if (sidx[k] < STG_F2) xs2[sidx[k]] = pre[k];

    int p = 0;
    for (int st = 0; st < TST; st++) {
        __syncthreads();
        if (st + 1 < TST) {
            const float* xsrc = xb0 + (size_t)(st+1)*4*HW;
            #pragma unroll
            for (int k = 0; k < 7; k++)
                pre[k] = gval[k] ? *(const float2*)(xsrc + goff[k]) : make_float2(0.f, 0.f);
        }
        const float* buf = (const float*)(xs2 + p*STG_F2);
        #pragma unroll
        for (int ci = 0; ci < 4; ci++) {
            ull acc = 0ULL;
            #pragma unroll
            for (int i = 0; i < KK; i++) {
                const float* rw = buf + ((ci*11 + rp + i)*60 + w0);
                float2 A  = *(const float2*)rw;
                float2 Bv = *(const float2*)(rw + 2);
                float2 Cv = *(const float2*)(rw + 4);
                ull u0 = packf2(A.x,  A.y);
                ull u1 = packf2(A.y,  Bv.x);
                ull u2 = packf2(Bv.x, Bv.y);
                ull u3 = packf2(Bv.y, Cv.x);
                ull u4 = packf2(Cv.x, Cv.y);
                FMA2(acc, u0, dd[i*5+0]);
                FMA2(acc, u1, dd[i*5+1]);
                FMA2(acc, u2, dd[i*5+2]);
                FMA2(acc, u3, dd[i*5+3]);
                FMA2(acc, u4, dd[i*5+4]);
            }
            float2 o = unpackf2(acc);
            *(float2*)(ob + (size_t)(c0 + st*4 + ci)*HW + h*WW + w0) = o;
        }
        if (st + 1 < TST) {
            float2* dst = xs2 + (1-p)*STG_F2;
            #pragma unroll
            for (int k = 0; k < 7; k++)
                if (sidx[k] < STG_F2) dst[sidx[k]] = pre[k];
        }
        p ^= 1;
    }
}

// ---------------------------------------------------------------------------
extern "C" void kernel_launch(void* const* d_in, const int* in_sizes, int n_in,
                              void* d_out, int out_size) {
    const float* x   = (const float*)d_in[0];
    const float* ctx = (const float*)d_in[1];
    const float* Wq  = (const float*)d_in[2];
    const float* Wk  = (const float*)d_in[3];
    const float* Wwd = (const float*)d_in[4];
    float* out = (float*)d_out;

    static bool attr_set = false;
    if (!attr_set) {
        cudaFuncSetAttribute(attn_kernel,
                             cudaFuncAttributeMaxDynamicSharedMemorySize,
                             ATTN_SMEM);
        attr_set = true;
    }

    pool_kernel<<<BB*CC, 256>>>(ctx);
    kf_kernel<<<(BB*D2*SS2 + 255)/256, 256>>>(Wk);
    m_kernel<<<(BB*CC*SPM + 255)/256, 256>>>(Wq);
    attn_kernel<<<dim3(HW/PX, BB), AT, ATTN_SMEM>>>(x, Wwd);
    taps_kernel<<<dim3(CC/TCG, HH/7, BB), TT>>>(x, out);
}

// round 7
// speedup vs baseline: 3.1782x; 1.2760x over previous
#include <cuda_runtime.h>
#include <cstdint>

typedef unsigned long long ull;

#define BB 4
#define CC 384
#define HH 56
#define WW 56
#define HW (HH*WW)   // 3136
#define KK 5
#define KK2 25
#define SS 7
#define SS2 49
#define D2 192
#define SPM 64       // padded M row: 4 segments x 16 slots (14 real + 2 pad)
#define SEG 14

__device__ __align__(16) float g_ctx_p[BB*CC*SS2];
__device__ __align__(16) float g_kf[BB*D2*SS2];
__device__ __align__(16) float g_M[BB*CC*SPM];
__device__ __align__(16) float g_dyn[BB*KK2*HW];

#define FMA2(acc, a, b) asm("fma.rn.f32x2 %0, %1, %2, %0;" : "+l"(acc) : "l"(a), "l"(b))

__device__ __forceinline__ ull packf2(float lo, float hi) {
    ull r;
    asm("mov.b64 %0, {%1, %2};" : "=l"(r) : "r"(__float_as_uint(lo)), "r"(__float_as_uint(hi)));
    return r;
}
__device__ __forceinline__ float2 unpackf2(ull v) {
    uint32_t l, h;
    asm("mov.b64 {%0, %1}, %2;" : "=r"(l), "=r"(h) : "l"(v));
    float2 r; r.x = __uint_as_float(l); r.y = __uint_as_float(h);
    return r;
}

// ---------------------------------------------------------------------------
// K1 v2: adaptive avg pool, atomic-free.
// Block 256 thr per (b,c). Warp w owns rows {w, w+8, ..., w+48}.
// Lane l<28 reads float2 (cols 2l,2l+1); 2x shfl.bfly reduces 4-lane groups
// (one 8-col bin each); lane l%4==0 stores bin directly. Phase 2: 49 threads
// sum 8 row-partials per (s1,s2).
// ---------------------------------------------------------------------------
__global__ void __launch_bounds__(256) pool_kernel(const float* __restrict__ ctx) {
    __shared__ float part[HH][SS];
    int t = threadIdx.x;
    int w = t >> 5;
    int l = t & 31;
    int bc = blockIdx.x;
    const float* p = ctx + (size_t)bc * HW;

    #pragma unroll
    for (int it = 0; it < 7; it++) {
        int h = w + it*8;
        float v = 0.f;
        if (l < 28) {
            float2 d2 = *(const float2*)(p + h*WW + 2*l);
            v = d2.x + d2.y;
        }
        v += __shfl_xor_sync(0xFFFFFFFFu, v, 1);
        v += __shfl_xor_sync(0xFFFFFFFFu, v, 2);
        if (l < 28 && (l & 3) == 0)
            part[h][l >> 2] = v;
    }
    __syncthreads();
    if (t < SS2) {
        int s1 = t / SS, s2 = t - s1*SS;
        float s = 0.f;
        #pragma unroll
        for (int i = 0; i < 8; i++) s += part[s1*8 + i][s2];
        g_ctx_p[(size_t)bc * SS2 + t] = s * (1.f/64.f);
    }
}

// ---------------------------------------------------------------------------
// K2: kf[b,d,s] = sum_c Wk[d,c] * ctx_p[b,c,s]
// ---------------------------------------------------------------------------
__global__ void kf_kernel(const float* __restrict__ Wk) {
    int id = blockIdx.x * blockDim.x + threadIdx.x;
    if (id >= BB*D2*SS2) return;
    int s = id % SS2;
    int d = (id / SS2) % D2;
    int b = id / (SS2*D2);
    const float* wk = Wk + (size_t)d * CC;
    const float* cp = g_ctx_p + (size_t)b * CC * SS2 + s;
    float acc = 0.f;
    #pragma unroll 8
    for (int c = 0; c < CC; c++) acc += wk[c] * cp[(size_t)c * SS2];
    g_kf[id] = acc;
}

// ---------------------------------------------------------------------------
// K3: M[b,c,slot] with slot = sg*16+k -> s = sg*14+k (k<14, s<49), pads 0
// ---------------------------------------------------------------------------
__global__ void m_kernel(const float* __restrict__ Wq) {
    int id = blockIdx.x * blockDim.x + threadIdx.x;
    if (id >= BB*CC*SPM) return;
    int slot = id % SPM;
    int c = (id / SPM) % CC;
    int b = id / (SPM*CC);
    int sg = slot >> 4, k = slot & 15;
    int s = sg*SEG + k;
    float acc = 0.f;
    if (k < SEG && s < SS2) {
        const float* kf = g_kf + (size_t)b * D2 * SS2 + s;
        #pragma unroll 8
        for (int d = 0; d < D2; d++) acc += Wq[(size_t)d * CC + c] * kf[(size_t)d * SS2];
    }
    g_M[id] = acc;
}

// ---------------------------------------------------------------------------
// K4 v4: PX=32 pixels/block, 64 threads, grid 392. Thread = 2 px x 14 s
// (7 f32x2 accs per pixel). Double-buffered 16-channel chunks in smem.
// ---------------------------------------------------------------------------
#define PX 32
#define AT 64
#define KCH 16
#define NCH (CC/KCH)          // 24
#define XS_F (KCH*PX)         // 512 floats per buffer
#define MS_F (KCH*SPM)        // 1024 floats per buffer
#define PSTR 57

__global__ void __launch_bounds__(AT) attn_kernel(const float* __restrict__ x,
                                                  const float* __restrict__ Wwd) {
    __shared__ __align__(16) float xs[2*XS_F];
    __shared__ __align__(16) float ms[2*MS_F];
    __shared__ float part[PX*PSTR];
    __shared__ float wwd[KK2*SS2];

    int t = threadIdx.x;
    int pxp = t & 15;       // pixel pair -> pixels 2pxp, 2pxp+1
    int sg  = t >> 4;       // 0..3 -> s slots sg*16 .. +13
    int b = blockIdx.y;
    int n0 = blockIdx.x * PX;

    for (int i = t; i < KK2*SS2; i += AT) wwd[i] = Wwd[i];

    const float* xb = x + (size_t)b*CC*HW + n0;
    const float4* mb4 = (const float4*)(g_M + (size_t)b*CC*SPM);

    // prefetch mapping: xs float4 idx i: c=i/8, px4=i%8. ms float4 j: linear.
    int xc0 = t >> 3,        xq0 = t & 7;
    int xc1 = (t+64) >> 3,   xq1 = (t+64) & 7;

    float4 pf0, pf1, pm0, pm1, pm2, pm3;
    pf0 = *(const float4*)(xb + (size_t)xc0*HW + xq0*4);
    pf1 = *(const float4*)(xb + (size_t)xc1*HW + xq1*4);
    pm0 = mb4[t]; pm1 = mb4[t+64]; pm2 = mb4[t+128]; pm3 = mb4[t+192];
    {
        float4* xs4 = (float4*)xs;
        float4* ms4 = (float4*)ms;
        xs4[t] = pf0; xs4[t+64] = pf1;
        ms4[t] = pm0; ms4[t+64] = pm1; ms4[t+128] = pm2; ms4[t+192] = pm3;
    }

    ull acc0[7], acc1[7];
    #pragma unroll
    for (int j = 0; j < 7; j++) { acc0[j] = 0ULL; acc1[j] = 0ULL; }

    uint32_t xs_sa = (uint32_t)__cvta_generic_to_shared(xs) + pxp*8;
    uint32_t ms_sa = (uint32_t)__cvta_generic_to_shared(ms) + sg*64;

    int p = 0;
    for (int ch = 0; ch < NCH; ch++) {
        __syncthreads();
        if (ch + 1 < NCH) {
            const float* xcb = xb + (size_t)(ch+1)*KCH*HW;
            const float4* mcb = mb4 + (ch+1)*(MS_F/4);
            pf0 = *(const float4*)(xcb + (size_t)xc0*HW + xq0*4);
            pf1 = *(const float4*)(xcb + (size_t)xc1*HW + xq1*4);
            pm0 = mcb[t]; pm1 = mcb[t+64]; pm2 = mcb[t+128]; pm3 = mcb[t+192];
        }
        uint32_t xsa = xs_sa + p*(XS_F*4);
        uint32_t msa = ms_sa + p*(MS_F*4);
        #pragma unroll
        for (int c = 0; c < KCH; c++) {
            float xv0, xv1;
            asm("ld.shared.v2.f32 {%0, %1}, [%2];"
                : "=f"(xv0), "=f"(xv1) : "r"(xsa + c*(PX*4)));
            ull ax0 = packf2(xv0, xv0);
            ull ax1 = packf2(xv1, xv1);
            ull m0,m1,m2,m3,m4,m5,m6;
            uint32_t ma = msa + c*(SPM*4);
            asm("ld.shared.v2.u64 {%0, %1}, [%2];" : "=l"(m0), "=l"(m1) : "r"(ma));
            asm("ld.shared.v2.u64 {%0, %1}, [%2];" : "=l"(m2), "=l"(m3) : "r"(ma+16));
            asm("ld.shared.v2.u64 {%0, %1}, [%2];" : "=l"(m4), "=l"(m5) : "r"(ma+32));
            asm("ld.shared.u64 %0, [%1];"          : "=l"(m6)           : "r"(ma+48));
            FMA2(acc0[0], ax0, m0);  FMA2(acc1[0], ax1, m0);
            FMA2(acc0[1], ax0, m1);  FMA2(acc1[1], ax1, m1);
            FMA2(acc0[2], ax0, m2);  FMA2(acc1[2], ax1, m2);
            FMA2(acc0[3], ax0, m3);  FMA2(acc1[3], ax1, m3);
            FMA2(acc0[4], ax0, m4);  FMA2(acc1[4], ax1, m4);
            FMA2(acc0[5], ax0, m5);  FMA2(acc1[5], ax1, m5);
            FMA2(acc0[6], ax0, m6);  FMA2(acc1[6], ax1, m6);
        }
        if (ch + 1 < NCH) {
            float4* xs4 = (float4*)(xs + (1-p)*XS_F);
            float4* ms4 = (float4*)(ms + (1-p)*MS_F);
            xs4[t] = pf0; xs4[t+64] = pf1;
            ms4[t] = pm0; ms4[t+64] = pm1; ms4[t+128] = pm2; ms4[t+192] = pm3;
        }
        p ^= 1;
    }

    // scatter logits
    {
        float* pr0 = part + (2*pxp)*PSTR + sg*SEG;
        float* pr1 = pr0 + PSTR;
        #pragma unroll
        for (int j = 0; j < 7; j++) {
            float2 v0 = unpackf2(acc0[j]);
            float2 v1 = unpackf2(acc1[j]);
            pr0[2*j] = v0.x; pr0[2*j+1] = v0.y;
            pr1[2*j] = v1.x; pr1[2*j+1] = v1.y;
        }
    }
    __syncthreads();

    // softmax per pixel (threads 0..31)
    if (t < PX) {
        float* row = part + t*PSTR;
        float v[SS2];
        #pragma unroll
        for (int s = 0; s < SS2; s++) v[s] = row[s];
        float mx = v[0];
        #pragma unroll
        for (int s = 1; s < SS2; s++) mx = fmaxf(mx, v[s]);
        float sum = 0.f;
        #pragma unroll
        for (int s = 0; s < SS2; s++) { v[s] = __expf(v[s] - mx); sum += v[s]; }
        #pragma unroll
        for (int s = 0; s < SS2; s++) row[s] = v[s];
        row[56] = 1.f / sum;
    }
    __syncthreads();

    // dyn projection
    for (int idx = t; idx < KK2*PX; idx += AT) {
        int px = idx & 31;
        int j  = idx >> 5;
        const float* ww  = wwd + j*SS2;
        const float* row = part + px*PSTR;
        float d = 0.f;
        #pragma unroll
        for (int s = 0; s < SS2; s++) d += ww[s] * row[s];
        g_dyn[((size_t)b*KK2 + j)*HW + n0 + px] = d * row[56];
    }
}

// ---------------------------------------------------------------------------
// K5 v3: f32x2 taps (unchanged from R5).
// ---------------------------------------------------------------------------
#define TT 196
#define TCG 24
#define TST 6
#define STG_F2 1320

__global__ void __launch_bounds__(TT, 3) taps_kernel(const float* __restrict__ x,
                                                     float* __restrict__ out) {
    __shared__ float2 xs2[2*STG_F2];
    int t = threadIdx.x;
    int rp = t / 28;
    int wp = t % 28;
    int w0 = wp*2;
    int b  = blockIdx.z;
    int h0 = blockIdx.y * 7;
    int c0 = blockIdx.x * TCG;
    int h  = h0 + rp;

    ull dd[KK2];
    #pragma unroll
    for (int j = 0; j < KK2; j++)
        dd[j] = *(const ull*)(g_dyn + ((size_t)b*KK2 + j)*HW + h*WW + w0);

    int sidx[7]; int goff[7]; bool gval[7];
    #pragma unroll
    for (int k = 0; k < 7; k++) {
        int idx = t + TT*k;
        sidx[k] = idx;
        int ci  = idx / 330;
        int rem = idx - ci*330;
        int rr  = rem / 30;
        int q   = rem - rr*30;
        int gr  = h0 + rr - 2;
        int gc  = 2*q - 2;
        gval[k] = (idx < STG_F2) && (gr >= 0) && (gr < HH) && (q >= 1) && (q <= 28);
        goff[k] = ci*HW + gr*WW + gc;
    }

    const float* xb0 = x + (size_t)b*CC*HW + (size_t)c0*HW;
    float* ob = out + (size_t)b*CC*HW;

    float2 pre[7];
    #pragma unroll
    for (int k = 0; k < 7; k++)
        pre[k] = gval[k] ? *(const float2*)(xb0 + goff[k]) : make_float2(0.f, 0.f);
    #pragma unroll
    for (int k = 0; k < 7; k++)
        if (sidx[k] < STG_F2) xs2[sidx[k]] = pre[k];

    int p = 0;
    for (int st = 0; st < TST; st++) {
        __syncthreads();
        if (st + 1 < TST) {
            const float* xsrc = xb0 + (size_t)(st+1)*4*HW;
            #pragma unroll
            for (int k = 0; k < 7; k++)
                pre[k] = gval[k] ? *(const float2*)(xsrc + goff[k]) : make_float2(0.f, 0.f);
        }
        const float* buf = (const float*)(xs2 + p*STG_F2);
        #pragma unroll
        for (int ci = 0; ci < 4; ci++) {
            ull acc = 0ULL;
            #pragma unroll
            for (int i = 0; i < KK; i++) {
                const float* rw = buf + ((ci*11 + rp + i)*60 + w0);
                float2 A  = *(const float2*)rw;
                float2 Bv = *(const float2*)(rw + 2);
                float2 Cv = *(const float2*)(rw + 4);
                ull u0 = packf2(A.x,  A.y);
                ull u1 = packf2(A.y,  Bv.x);
                ull u2 = packf2(Bv.x, Bv.y);
                ull u3 = packf2(Bv.y, Cv.x);
                ull u4 = packf2(Cv.x, Cv.y);
                FMA2(acc, u0, dd[i*5+0]);
                FMA2(acc, u1, dd[i*5+1]);
                FMA2(acc, u2, dd[i*5+2]);
                FMA2(acc, u3, dd[i*5+3]);
                FMA2(acc, u4, dd[i*5+4]);
            }
            float2 o = unpackf2(acc);
            *(float2*)(ob + (size_t)(c0 + st*4 + ci)*HW + h*WW + w0) = o;
        }
        if (st + 1 < TST) {
            float2* dst = xs2 + (1-p)*STG_F2;
            #pragma unroll
            for (int k = 0; k < 7; k++)
                if (sidx[k] < STG_F2) dst[sidx[k]] = pre[k];
        }
        p ^= 1;
    }
}

// ---------------------------------------------------------------------------
extern "C" void kernel_launch(void* const* d_in, const int* in_sizes, int n_in,
                              void* d_out, int out_size) {
    const float* x   = (const float*)d_in[0];
    const float* ctx = (const float*)d_in[1];
    const float* Wq  = (const float*)d_in[2];
    const float* Wk  = (const float*)d_in[3];
    const float* Wwd = (const float*)d_in[4];
    float* out = (float*)d_out;

    pool_kernel<<<BB*CC, 256>>>(ctx);
    kf_kernel<<<(BB*D2*SS2 + 255)/256, 256>>>(Wk);
    m_kernel<<<(BB*CC*SPM + 255)/256, 256>>>(Wq);
    attn_kernel<<<dim3(HW/PX, BB), AT>>>(x, Wwd);
    taps_kernel<<<dim3(CC/TCG, HH/7, BB), TT>>>(x, out);
}

// round 8
// speedup vs baseline: 3.2118x; 1.0106x over previous
#include <cuda_runtime.h>
#include <cstdint>

typedef unsigned long long ull;

#define BB 4
#define CC 384
#define HH 56
#define WW 56
#define HW (HH*WW)   // 3136
#define KK 5
#define KK2 25
#define SS 7
#define SS2 49
#define D2 192
#define SPM 64       // padded M row: 4 segments x 16 slots (14 real + 2 pad)
#define SEG 14

__device__ __align__(16) float g_ctx_p[BB*CC*SS2];
__device__ __align__(16) float g_kf[BB*D2*SS2];
__device__ __align__(16) float g_M[BB*CC*SPM];
__device__ __align__(16) float g_dyn[BB*KK2*HW];

#define FMA2(acc, a, b) asm("fma.rn.f32x2 %0, %1, %2, %0;" : "+l"(acc) : "l"(a), "l"(b))

__device__ __forceinline__ ull packf2(float lo, float hi) {
    ull r;
    asm("mov.b64 %0, {%1, %2};" : "=l"(r) : "r"(__float_as_uint(lo)), "r"(__float_as_uint(hi)));
    return r;
}
__device__ __forceinline__ float2 unpackf2(ull v) {
    uint32_t l, h;
    asm("mov.b64 {%0, %1}, %2;" : "=r"(l), "=r"(h) : "l"(v));
    float2 r; r.x = __uint_as_float(l); r.y = __uint_as_float(h);
    return r;
}

// ---------------------------------------------------------------------------
// K1 v2: adaptive avg pool, atomic-free (shfl reduce).
// ---------------------------------------------------------------------------
__global__ void __launch_bounds__(256) pool_kernel(const float* __restrict__ ctx) {
    __shared__ float part[HH][SS];
    int t = threadIdx.x;
    int w = t >> 5;
    int l = t & 31;
    int bc = blockIdx.x;
    const float* p = ctx + (size_t)bc * HW;

    #pragma unroll
    for (int it = 0; it < 7; it++) {
        int h = w + it*8;
        float v = 0.f;
        if (l < 28) {
            float2 d2 = *(const float2*)(p + h*WW + 2*l);
            v = d2.x + d2.y;
        }
        v += __shfl_xor_sync(0xFFFFFFFFu, v, 1);
        v += __shfl_xor_sync(0xFFFFFFFFu, v, 2);
        if (l < 28 && (l & 3) == 0)
            part[h][l >> 2] = v;
    }
    __syncthreads();
    if (t < SS2) {
        int s1 = t / SS, s2 = t - s1*SS;
        float s = 0.f;
        #pragma unroll
        for (int i = 0; i < 8; i++) s += part[s1*8 + i][s2];
        g_ctx_p[(size_t)bc * SS2 + t] = s * (1.f/64.f);
    }
}

// ---------------------------------------------------------------------------
// K2: kf[b,d,s] = sum_c Wk[d,c] * ctx_p[b,c,s]
// ---------------------------------------------------------------------------
__global__ void kf_kernel(const float* __restrict__ Wk) {
    int id = blockIdx.x * blockDim.x + threadIdx.x;
    if (id >= BB*D2*SS2) return;
    int s = id % SS2;
    int d = (id / SS2) % D2;
    int b = id / (SS2*D2);
    const float* wk = Wk + (size_t)d * CC;
    const float* cp = g_ctx_p + (size_t)b * CC * SS2 + s;
    float acc = 0.f;
    #pragma unroll 8
    for (int c = 0; c < CC; c++) acc += wk[c] * cp[(size_t)c * SS2];
    g_kf[id] = acc;
}

// ---------------------------------------------------------------------------
// K3: M[b,c,slot] with slot = sg*16+k -> s = sg*14+k (k<14, s<49), pads 0
// ---------------------------------------------------------------------------
__global__ void m_kernel(const float* __restrict__ Wq) {
    int id = blockIdx.x * blockDim.x + threadIdx.x;
    if (id >= BB*CC*SPM) return;
    int slot = id % SPM;
    int c = (id / SPM) % CC;
    int b = id / (SPM*CC);
    int sg = slot >> 4, k = slot & 15;
    int s = sg*SEG + k;
    float acc = 0.f;
    if (k < SEG && s < SS2) {
        const float* kf = g_kf + (size_t)b * D2 * SS2 + s;
        #pragma unroll 8
        for (int d = 0; d < D2; d++) acc += Wq[(size_t)d * CC + c] * kf[(size_t)d * SS2];
    }
    g_M[id] = acc;
}

// ---------------------------------------------------------------------------
// K4 v5: PX=32, 128 threads = (16 px-pairs) x (4 s-groups) x (2 c-halves).
// Each half accumulates 192 channels; combine via smem. Grid 392, 4 warps/blk.
// ---------------------------------------------------------------------------
#define PX 32
#define AT 128
#define KCH 16
#define NCH 12              // chunks of 16 c per half (192/16)
#define XS_F (2*KCH*PX)     // 1024 floats per stage ([half][c][px])
#define MS_F (2*KCH*SPM)    // 2048 floats per stage ([half][c][slot])
#define PSTR 57

__global__ void __launch_bounds__(AT) attn_kernel(const float* __restrict__ x,
                                                  const float* __restrict__ Wwd) {
    __shared__ __align__(16) float xs[2*XS_F];
    __shared__ __align__(16) float ms[2*MS_F];
    __shared__ float part[PX*PSTR];
    __shared__ float wwd[KK2*SS2];

    int t = threadIdx.x;
    int pxp = t & 15;           // pixel pair -> pixels 2pxp, 2pxp+1
    int sg  = (t >> 4) & 3;     // s slots sg*16 .. +13
    int cf  = t >> 6;           // channel half
    int b = blockIdx.y;
    int n0 = blockIdx.x * PX;

    for (int i = t; i < KK2*SS2; i += AT) wwd[i] = Wwd[i];

    const float* xb = x + (size_t)b*CC*HW + n0;
    const float4* mb4 = (const float4*)(g_M + (size_t)b*CC*SPM);

    // prefetch mapping (see layout notes): xs4[t]=(h0,xc,xq), xs4[t+128]=(h1,xc,xq)
    int xc = t >> 3, xq = t & 7;          // xc 0..15, xq 0..7
    int mca = t >> 4, mq = t & 15;        // mca 0..7

    float4 pf0, pf1, pm0, pm1, pm2, pm3;
    pf0 = *(const float4*)(xb + (size_t)xc*HW + xq*4);
    pf1 = *(const float4*)(xb + (size_t)(D2 + xc)*HW + xq*4);
    pm0 = mb4[(mca)*16 + mq];
    pm1 = mb4[(mca + 8)*16 + mq];
    pm2 = mb4[(D2 + mca)*16 + mq];
    pm3 = mb4[(D2 + mca + 8)*16 + mq];
    {
        float4* xs4 = (float4*)xs;
        float4* ms4 = (float4*)ms;
        xs4[t] = pf0; xs4[t+128] = pf1;
        ms4[t] = pm0; ms4[t+128] = pm1; ms4[t+256] = pm2; ms4[t+384] = pm3;
    }

    ull acc0[7], acc1[7];
    #pragma unroll
    for (int j = 0; j < 7; j++) { acc0[j] = 0ULL; acc1[j] = 0ULL; }

    uint32_t xs_sa = (uint32_t)__cvta_generic_to_shared(xs) + (cf*(KCH*PX) + pxp*2)*4;
    uint32_t ms_sa = (uint32_t)__cvta_generic_to_shared(ms) + (cf*(KCH*SPM) + sg*16)*4;

    int p = 0;
    for (int ch = 0; ch < NCH; ch++) {
        __syncthreads();
        if (ch + 1 < NCH) {
            int cb = (ch+1)*KCH;
            pf0 = *(const float4*)(xb + (size_t)(cb + xc)*HW + xq*4);
            pf1 = *(const float4*)(xb + (size_t)(D2 + cb + xc)*HW + xq*4);
            pm0 = mb4[(cb + mca)*16 + mq];
            pm1 = mb4[(cb + mca + 8)*16 + mq];
            pm2 = mb4[(D2 + cb + mca)*16 + mq];
            pm3 = mb4[(D2 + cb + mca + 8)*16 + mq];
        }
        uint32_t xsa = xs_sa + p*(XS_F*4);
        uint32_t msa = ms_sa + p*(MS_F*4);
        #pragma unroll
        for (int c = 0; c < KCH; c++) {
            float xv0, xv1;
            asm("ld.shared.v2.f32 {%0, %1}, [%2];"
                : "=f"(xv0), "=f"(xv1) : "r"(xsa + c*(PX*4)));
            ull ax0 = packf2(xv0, xv0);
            ull ax1 = packf2(xv1, xv1);
            ull m0,m1,m2,m3,m4,m5,m6;
            uint32_t ma = msa + c*(SPM*4);
            asm("ld.shared.v2.u64 {%0, %1}, [%2];" : "=l"(m0), "=l"(m1) : "r"(ma));
            asm("ld.shared.v2.u64 {%0, %1}, [%2];" : "=l"(m2), "=l"(m3) : "r"(ma+16));
            asm("ld.shared.v2.u64 {%0, %1}, [%2];" : "=l"(m4), "=l"(m5) : "r"(ma+32));
            asm("ld.shared.u64 %0, [%1];"          : "=l"(m6)           : "r"(ma+48));
            FMA2(acc0[0], ax0, m0);  FMA2(acc1[0], ax1, m0);
            FMA2(acc0[1], ax0, m1);  FMA2(acc1[1], ax1, m1);
            FMA2(acc0[2], ax0, m2);  FMA2(acc1[2], ax1, m2);
            FMA2(acc0[3], ax0, m3);  FMA2(acc1[3], ax1, m3);
            FMA2(acc0[4], ax0, m4);  FMA2(acc1[4], ax1, m4);
            FMA2(acc0[5], ax0, m5);  FMA2(acc1[5], ax1, m5);
            FMA2(acc0[6], ax0, m6);  FMA2(acc1[6], ax1, m6);
        }
        if (ch + 1 < NCH) {
            float4* xs4 = (float4*)(xs + (1-p)*XS_F);
            float4* ms4 = (float4*)(ms + (1-p)*MS_F);
            xs4[t] = pf0; xs4[t+128] = pf1;
            ms4[t] = pm0; ms4[t+128] = pm1; ms4[t+256] = pm2; ms4[t+384] = pm3;
        }
        p ^= 1;
    }

    // combine halves into part: half0 writes, half1 read-add-writes
    {
        float* pr0 = part + (2*pxp)*PSTR + sg*SEG;
        float* pr1 = pr0 + PSTR;
        if (cf == 0) {
            #pragma unroll
            for (int j = 0; j < 7; j++) {
                float2 v0 = unpackf2(acc0[j]);
                float2 v1 = unpackf2(acc1[j]);
                pr0[2*j] = v0.x; pr0[2*j+1] = v0.y;
                pr1[2*j] = v1.x; pr1[2*j+1] = v1.y;
            }
        }
        __syncthreads();
        if (cf == 1) {
            #pragma unroll
            for (int j = 0; j < 7; j++) {
                float2 v0 = unpackf2(acc0[j]);
                float2 v1 = unpackf2(acc1[j]);
                pr0[2*j] += v0.x; pr0[2*j+1] += v0.y;
                pr1[2*j] += v1.x; pr1[2*j+1] += v1.y;
            }
        }
    }
    __syncthreads();

    // softmax per pixel (threads 0..31)
    if (t < PX) {
        float* row = part + t*PSTR;
        float v[SS2];
        #pragma unroll
        for (int s = 0; s < SS2; s++) v[s] = row[s];
        float mx = v[0];
        #pragma unroll
        for (int s = 1; s < SS2; s++) mx = fmaxf(mx, v[s]);
        float sum = 0.f;
        #pragma unroll
        for (int s = 0; s < SS2; s++) { v[s] = __expf(v[s] - mx); sum += v[s]; }
        #pragma unroll
        for (int s = 0; s < SS2; s++) row[s] = v[s];
        row[56] = 1.f / sum;
    }
    __syncthreads();

    // dyn projection (800 outputs over 128 threads)
    for (int idx = t; idx < KK2*PX; idx += AT) {
        int px = idx & 31;
        int j  = idx >> 5;
        const float* ww  = wwd + j*SS2;
        const float* row = part + px*PSTR;
        float d = 0.f;
        #pragma unroll
        for (int s = 0; s < SS2; s++) d += ww[s] * row[s];
        g_dyn[((size_t)b*KK2 + j)*HW + n0 + px] = d * row[56];
    }
}

// ---------------------------------------------------------------------------
// K5 v4: f32x2 taps, dual accumulator chains (even/odd rows).
// ---------------------------------------------------------------------------
#define TT 196
#define TCG 24
#define TST 6
#define STG_F2 1320

__global__ void __launch_bounds__(TT, 3) taps_kernel(const float* __restrict__ x,
                                                     float* __restrict__ out) {
    __shared__ float2 xs2[2*STG_F2];
    int t = threadIdx.x;
    int rp = t / 28;
    int wp = t % 28;
    int w0 = wp*2;
    int b  = blockIdx.z;
    int h0 = blockIdx.y * 7;
    int c0 = blockIdx.x * TCG;
    int h  = h0 + rp;

    ull dd[KK2];
    #pragma unroll
    for (int j = 0; j < KK2; j++)
        dd[j] = *(const ull*)(g_dyn + ((size_t)b*KK2 + j)*HW + h*WW + w0);

    int sidx[7]; int goff[7]; bool gval[7];
    #pragma unroll
    for (int k = 0; k < 7; k++) {
        int idx = t + TT*k;
        sidx[k] = idx;
        int ci  = idx / 330;
        int rem = idx - ci*330;
        int rr  = rem / 30;
        int q   = rem - rr*30;
        int gr  = h0 + rr - 2;
        int gc  = 2*q - 2;
        gval[k] = (idx < STG_F2) && (gr >= 0) && (gr < HH) && (q >= 1) && (q <= 28);
        goff[k] = ci*HW + gr*WW + gc;
    }

    const float* xb0 = x + (size_t)b*CC*HW + (size_t)c0*HW;
    float* ob = out + (size_t)b*CC*HW;

    float2 pre[7];
    #pragma unroll
    for (int k = 0; k < 7; k++)
        pre[k] = gval[k] ? *(const float2*)(xb0 + goff[k]) : make_float2(0.f, 0.f);
    #pragma unroll
    for (int k = 0; k < 7; k++)
        if (sidx[k] < STG_F2) xs2[sidx[k]] = pre[k];

    int p = 0;
    for (int st = 0; st < TST; st++) {
        __syncthreads();
        if (st + 1 < TST) {
            const float* xsrc = xb0 + (size_t)(st+1)*4*HW;
            #pragma unroll
            for (int k = 0; k < 7; k++)
                pre[k] = gval[k] ? *(const float2*)(xsrc + goff[k]) : make_float2(0.f, 0.f);
        }
        const float* buf = (const float*)(xs2 + p*STG_F2);
        #pragma unroll
        for (int ci = 0; ci < 4; ci++) {
            ull accA = 0ULL, accB = 0ULL;
            #pragma unroll
            for (int i = 0; i < KK; i++) {
                const float* rw = buf + ((ci*11 + rp + i)*60 + w0);
                float2 A  = *(const float2*)rw;
                float2 Bv = *(const float2*)(rw + 2);
                float2 Cv = *(const float2*)(rw + 4);
                ull u0 = packf2(A.x,  A.y);
                ull u1 = packf2(A.y,  Bv.x);
                ull u2 = packf2(Bv.x, Bv.y);
                ull u3 = packf2(Bv.y, Cv.x);
                ull u4 = packf2(Cv.x, Cv.y);
                ull& acc = (i & 1) ? accB : accA;
                FMA2(acc, u0, dd[i*5+0]);
                FMA2(acc, u1, dd[i*5+1]);
                FMA2(acc, u2, dd[i*5+2]);
                FMA2(acc, u3, dd[i*5+3]);
                FMA2(acc, u4, dd[i*5+4]);
            }
            float2 oa = unpackf2(accA);
            float2 obv = unpackf2(accB);
            float2 o; o.x = oa.x + obv.x; o.y = oa.y + obv.y;
            *(float2*)(ob + (size_t)(c0 + st*4 + ci)*HW + h*WW + w0) = o;
        }
        if (st + 1 < TST) {
            float2* dst = xs2 + (1-p)*STG_F2;
            #pragma unroll
            for (int k = 0; k < 7; k++)
                if (sidx[k] < STG_F2) dst[sidx[k]] = pre[k];
        }
        p ^= 1;
    }
}

// ---------------------------------------------------------------------------
extern "C" void kernel_launch(void* const* d_in, const int* in_sizes, int n_in,
                              void* d_out, int out_size) {
    const float* x   = (const float*)d_in[0];
    const float* ctx = (const float*)d_in[1];
    const float* Wq  = (const float*)d_in[2];
    const float* Wk  = (const float*)d_in[3];
    const float* Wwd = (const float*)d_in[4];
    float* out = (float*)d_out;

    pool_kernel<<<BB*CC, 256>>>(ctx);
    kf_kernel<<<(BB*D2*SS2 + 255)/256, 256>>>(Wk);
    m_kernel<<<(BB*CC*SPM + 255)/256, 256>>>(Wq);
    attn_kernel<<<dim3(HW/PX, BB), AT>>>(x, Wwd);
    taps_kernel<<<dim3(CC/TCG, HH/7, BB), TT>>>(x, out);
}